// round 1
// baseline (speedup 1.0000x reference)
#include <cuda_runtime.h>
#include <math.h>

// ---------------------------------------------------------------------------
// SinkhornDistance: N=4, P1=P2=1024, D=16, EPS=0.1, MAX_ITER=100, THRESH=0.1
// Outputs (concatenated fp32): cost[4], pi[4*1024*1024], C[4*1024*1024]
// ---------------------------------------------------------------------------

#define NB 4
#define P  1024
#define DD 16
#define EPSF 0.1f
#define L2E_OVER_EPS 14.426950408889634f   // log2(e)/eps
#define LN2F 0.6931471805599453f
#define MAX_ITER 100
#define THRESHF 0.1f
#define SBLOCKS 128
#define STHREADS 1024
#define PLANE (NB*P*P)

// ----------------------------- scratch (static device memory, no allocs) ----
__device__ float    g_CT[PLANE];          // transposed cost matrix (16 MB)
__device__ float    g_u[NB*P];
__device__ float    g_v[NB*P];
__device__ float    g_logmu[NB*P];
__device__ float    g_lognu[NB*P];
__device__ float    g_errPart[SBLOCKS];
__device__ float    g_rowPart[NB*P];
__device__ int      g_done;
__device__ unsigned g_barCount;
__device__ unsigned g_barGen;

// ----------------------------- helpers --------------------------------------
__device__ __forceinline__ float ex2(float x) {
    float r; asm("ex2.approx.ftz.f32 %0, %1;" : "=f"(r) : "f"(x)); return r;
}
__device__ __forceinline__ float lg2(float x) {
    float r; asm("lg2.approx.ftz.f32 %0, %1;" : "=f"(r) : "f"(x)); return r;
}

// Grid-wide barrier for a co-resident persistent grid (SBLOCKS <= #SMs).
__device__ __forceinline__ void grid_barrier() {
    __syncthreads();
    if (threadIdx.x == 0) {
        __threadfence();
        unsigned gen = *(volatile unsigned*)&g_barGen;
        if (atomicAdd(&g_barCount, 1u) == SBLOCKS - 1) {
            *(volatile unsigned*)&g_barCount = 0;
            __threadfence();
            *(volatile unsigned*)&g_barGen = gen + 1;
        } else {
            while (*(volatile unsigned*)&g_barGen == gen) { }
            __threadfence();
        }
    }
    __syncthreads();
}

// eps * LSE_j((sh[j] - row[j]) / eps) over 1024 elements, warp-collective.
// Deterministic: fixed per-lane order + fixed shfl butterfly.
__device__ __forceinline__ float row_eps_lse(const float* __restrict__ row,
                                             const float* __restrict__ sh,
                                             int lane) {
    float t[32];
    float m = -1e30f;
#pragma unroll
    for (int k = 0; k < 8; ++k) {
        int idx = (k << 7) + (lane << 2);
        float4 c4 = *reinterpret_cast<const float4*>(row + idx);
        float4 s4 = *reinterpret_cast<const float4*>(sh + idx);
        float t0 = s4.x - c4.x, t1 = s4.y - c4.y;
        float t2 = s4.z - c4.z, t3 = s4.w - c4.w;
        t[(k << 2) + 0] = t0; t[(k << 2) + 1] = t1;
        t[(k << 2) + 2] = t2; t[(k << 2) + 3] = t3;
        m = fmaxf(m, fmaxf(fmaxf(t0, t1), fmaxf(t2, t3)));
    }
#pragma unroll
    for (int o = 16; o; o >>= 1) m = fmaxf(m, __shfl_xor_sync(0xffffffffu, m, o));
    float s = 0.f;
#pragma unroll
    for (int k = 0; k < 32; ++k) s += ex2((t[k] - m) * L2E_OVER_EPS);
#pragma unroll
    for (int o = 16; o; o >>= 1) s += __shfl_xor_sync(0xffffffffu, s, o);
    // eps * (m/eps + ln(s)) = m + eps*ln(s)
    return m + EPSF * (lg2(s) * LN2F);
}

// ----------------------------- kernel 0: init -------------------------------
__global__ void k_init(const float* __restrict__ wx, const float* __restrict__ wy) {
    int i = blockIdx.x * blockDim.x + threadIdx.x;   // 4096 threads total
    g_u[i] = 0.f;
    g_v[i] = 0.f;
    g_logmu[i] = logf(wx[i] + 1e-8f);
    g_lognu[i] = logf(wy[i] + 1e-8f);
    if (i == 0) g_done = 0;
}

// ----------------------------- kernel 1: cost matrix C and CT ---------------
__global__ void k_cost(const float* __restrict__ x, const float* __restrict__ y,
                       float* __restrict__ C) {
    __shared__ float xs[32][17];
    __shared__ float ys[32][17];
    __shared__ float tile[32][33];
    int n = blockIdx.z, I = blockIdx.y, J = blockIdx.x;
    int tid = threadIdx.x;   // 256

    for (int e = tid; e < 32 * DD; e += 256)
        xs[e >> 4][e & 15] = x[((size_t)(n * P + I * 32 + (e >> 4))) * DD + (e & 15)];
    for (int e = tid; e < 32 * DD; e += 256)
        ys[e >> 4][e & 15] = y[((size_t)(n * P + J * 32 + (e >> 4))) * DD + (e & 15)];
    __syncthreads();

    int ii = tid >> 3;
    int j0 = (tid & 7) * 4;
#pragma unroll
    for (int q = 0; q < 4; ++q) {
        int jj = j0 + q;
        float s = 0.f;
#pragma unroll
        for (int d = 0; d < DD; ++d) s += fabsf(xs[ii][d] - ys[jj][d]);
        tile[ii][jj] = s;
    }
    __syncthreads();

    for (int e = tid; e < 1024; e += 256) {
        int r = e >> 5, c = e & 31;
        C[((size_t)(n * P + I * 32 + r)) * P + (J * 32 + c)]   = tile[r][c];
        g_CT[((size_t)(n * P + J * 32 + r)) * P + (I * 32 + c)] = tile[c][r];
    }
}

// ----------------------------- kernel 2: persistent Sinkhorn loop -----------
__global__ void __launch_bounds__(STHREADS, 1)
k_sinkhorn(const float* __restrict__ C) {
    __shared__ __align__(16) float sh[P];
    __shared__ float sdu[32];
    __shared__ int   sdone;

    int tid = threadIdx.x;
    int w = tid >> 5, lane = tid & 31;
    int b = blockIdx.x;
    int r = b * 32 + w;                 // global row/col id, 0..4095
    int n = r >> 10;
    const float* crow  = C    + ((size_t)r << 10);
    const float* ctrow = g_CT + ((size_t)r << 10);
    float logmu = g_logmu[r];
    float lognu = g_lognu[r];
    float u_reg = 0.f;

    for (int it = 0; it < MAX_ITER; ++it) {
        // ---- u phase: stage v[n,:], row-LSE over C ----
        sh[tid] = __ldcg(&g_v[(n << 10) + tid]);
        __syncthreads();
        float lse = row_eps_lse(crow, sh, lane);
        float u_new = EPSF * logmu - lse;
        float du = fabsf(u_new - u_reg);
        u_reg = u_new;
        if (lane == 0) {
            __stcg(&g_u[r], u_new);
            sdu[w] = du;
        }
        __syncthreads();
        if (tid == 0) {
            float e = 0.f;
#pragma unroll
            for (int q = 0; q < 32; ++q) e += sdu[q];   // fixed order
            __stcg(&g_errPart[b], e);
        }
        grid_barrier();

        // ---- v phase: stage u[n,:], row-LSE over CT ----
        sh[tid] = __ldcg(&g_u[(n << 10) + tid]);
        __syncthreads();
        lse = row_eps_lse(ctrow, sh, lane);
        float v_new = EPSF * lognu - lse;
        if (lane == 0) __stcg(&g_v[r], v_new);

        if (b == 0 && tid == 0) {
            float e = 0.f;
            for (int q = 0; q < SBLOCKS; ++q) e += __ldcg(&g_errPart[q]); // fixed order
            __stcg(&g_done, (e * 0.25f < THRESHF) ? 1 : 0);
        }
        grid_barrier();

        if (tid == 0) sdone = __ldcg(&g_done);
        __syncthreads();
        if (sdone) break;   // uniform across the whole grid
    }
}

// ----------------------------- kernel 3: pi + per-row cost partials ---------
__global__ void k_pi(const float* __restrict__ C, float* __restrict__ pi) {
    __shared__ float vs[P];
    __shared__ float red[256];
    int r = blockIdx.x;
    int n = r >> 10;
    int tid = threadIdx.x;   // 256
    for (int e = tid; e < P; e += 256) vs[e] = g_v[(n << 10) + e];
    float u = g_u[r];
    __syncthreads();

    const float* crow = C + ((size_t)r << 10);
    float* prow = pi + ((size_t)r << 10);
    float acc = 0.f;
#pragma unroll
    for (int k = 0; k < 4; ++k) {
        int j = tid + (k << 8);
        float c = crow[j];
        float p = ex2((u + vs[j] - c) * L2E_OVER_EPS);
        prow[j] = p;
        acc += p * c;
    }
    red[tid] = acc;
    __syncthreads();
    for (int o = 128; o; o >>= 1) {
        if (tid < o) red[tid] += red[tid + o];
        __syncthreads();
    }
    if (tid == 0) g_rowPart[r] = red[0];
}

// ----------------------------- kernel 4: deterministic cost reduce ----------
__global__ void k_final(float* __restrict__ cost) {
    int tid = threadIdx.x;   // 128
    int n = tid >> 5, lane = tid & 31;
    float s = 0.f;
#pragma unroll
    for (int q = 0; q < 32; ++q) s += g_rowPart[(n << 10) + lane + (q << 5)];
#pragma unroll
    for (int o = 16; o; o >>= 1) s += __shfl_xor_sync(0xffffffffu, s, o);
    if (lane == 0) cost[n] = s;
}

// ----------------------------- launch ---------------------------------------
extern "C" void kernel_launch(void* const* d_in, const int* in_sizes, int n_in,
                              void* d_out, int out_size) {
    const float* x  = (const float*)d_in[0];
    const float* y  = (const float*)d_in[1];
    const float* wx = (const float*)d_in[2];
    const float* wy = (const float*)d_in[3];

    float* out  = (float*)d_out;
    float* cost = out;                 // [4]
    float* pi   = out + NB;            // [4,1024,1024]
    float* C    = out + NB + PLANE;    // [4,1024,1024]

    k_init<<<4, 1024>>>(wx, wy);
    dim3 gc(32, 32, 4);
    k_cost<<<gc, 256>>>(x, y, C);
    k_sinkhorn<<<SBLOCKS, STHREADS>>>(C);
    k_pi<<<NB * P, 256>>>(C, pi);
    k_final<<<1, 128>>>(cost);
}

// round 2
// speedup vs baseline: 1.1120x; 1.1120x over previous
#include <cuda_runtime.h>
#include <math.h>

// ---------------------------------------------------------------------------
// SinkhornDistance: N=4, P1=P2=1024, D=16, EPS=0.1, MAX_ITER=100, THRESH=0.1
// Outputs (concatenated fp32): cost[4], pi[4*1024*1024], C[4*1024*1024]
// Round 2: C resident in SMEM (128KB tile per persistent block); v-phase via
// per-block column partials + deterministic cross-block online-LSE merge.
// ---------------------------------------------------------------------------

#define NB 4
#define P  1024
#define DD 16
#define EPSF 0.1f
#define L2E_EPS 14.426950408889634f    // log2(e)/eps
#define EPSLN2 0.06931471805599453f    // eps*ln2
#define MAX_ITER 100
#define THRESHF 0.1f
#define SBLOCKS 128
#define STHREADS 1024
#define PLANE (NB*P*P)

// ----------------------------- scratch (static device memory) ---------------
__device__ float    g_u[NB*P];
__device__ float    g_v[NB*P];
__device__ float    g_logmu[NB*P];
__device__ float    g_lognu[NB*P];
__device__ float    g_errPart[SBLOCKS];
__device__ float    g_rowPart[NB*P];
__device__ float2   g_part[NB*P*32];     // [n][j][bb] (m,s) column partials
__device__ int      g_done;
__device__ unsigned g_barCount;
__device__ unsigned g_barGen;

// ----------------------------- helpers --------------------------------------
__device__ __forceinline__ float ex2(float x) {
    float r; asm("ex2.approx.ftz.f32 %0, %1;" : "=f"(r) : "f"(x)); return r;
}
__device__ __forceinline__ float lg2(float x) {
    float r; asm("lg2.approx.ftz.f32 %0, %1;" : "=f"(r) : "f"(x)); return r;
}

__device__ __forceinline__ void grid_barrier() {
    __syncthreads();
    if (threadIdx.x == 0) {
        __threadfence();
        unsigned gen = *(volatile unsigned*)&g_barGen;
        if (atomicAdd(&g_barCount, 1u) == SBLOCKS - 1) {
            *(volatile unsigned*)&g_barCount = 0;
            __threadfence();
            *(volatile unsigned*)&g_barGen = gen + 1;
        } else {
            while (*(volatile unsigned*)&g_barGen == gen) { }
            __threadfence();
        }
    }
    __syncthreads();
}

// ----------------------------- kernel 0: init -------------------------------
__global__ void k_init(const float* __restrict__ wx, const float* __restrict__ wy) {
    int i = blockIdx.x * blockDim.x + threadIdx.x;   // 4096 threads total
    g_u[i] = 0.f;
    g_v[i] = 0.f;
    g_logmu[i] = logf(wx[i] + 1e-8f);
    g_lognu[i] = logf(wy[i] + 1e-8f);
    if (i == 0) g_done = 0;
}

// ----------------------------- kernel 1: cost matrix C ----------------------
__global__ void k_cost(const float* __restrict__ x, const float* __restrict__ y,
                       float* __restrict__ C) {
    __shared__ float xs[32][17];
    __shared__ float ys[32][17];
    int n = blockIdx.z, I = blockIdx.y, J = blockIdx.x;
    int tid = threadIdx.x;   // 256

    for (int e = tid; e < 32 * DD; e += 256)
        xs[e >> 4][e & 15] = x[((size_t)(n * P + I * 32 + (e >> 4))) * DD + (e & 15)];
    for (int e = tid; e < 32 * DD; e += 256)
        ys[e >> 4][e & 15] = y[((size_t)(n * P + J * 32 + (e >> 4))) * DD + (e & 15)];
    __syncthreads();

    int ii = tid >> 3;
    int j0 = (tid & 7) * 4;
    float4 out;
    float* o = (float*)&out;
#pragma unroll
    for (int q = 0; q < 4; ++q) {
        int jj = j0 + q;
        float s = 0.f;
#pragma unroll
        for (int d = 0; d < DD; ++d) s += fabsf(xs[ii][d] - ys[jj][d]);
        o[q] = s;
    }
    *(float4*)&C[((size_t)(n * P + I * 32 + ii)) * P + (J * 32 + j0)] = out;
}

// ----------------------------- kernel 2: persistent Sinkhorn loop -----------
// SMEM: tile[32][1024] (C rows * log2e/eps) | shvs[1024] | sus[32] | sdu[32]
__global__ void __launch_bounds__(STHREADS, 1)
k_sink(const float* __restrict__ C) {
    extern __shared__ __align__(16) float smem[];
    float* tile = smem;                 // 32*1024
    float* shvs = smem + 32 * 1024;     // 1024
    float* sus  = shvs + 1024;          // 32 (scaled u of own rows)
    float* sdu  = sus + 32;             // 32
    __shared__ int sdone;

    int tid = threadIdx.x;
    int w = tid >> 5, lane = tid & 31;
    int b = blockIdx.x;
    int n = b >> 5, bb = b & 31;
    int r = (b << 5) + w;               // this warp's global row

    // load own 32 C rows into SMEM, pre-scaled by log2e/eps
    {
        const float4* src = (const float4*)(C + ((size_t)b << 15));
        float4* dst = (float4*)tile;
#pragma unroll
        for (int k = 0; k < 8; ++k) {
            float4 c = __ldcg(&src[tid + (k << 10)]);
            c.x *= L2E_EPS; c.y *= L2E_EPS; c.z *= L2E_EPS; c.w *= L2E_EPS;
            dst[tid + (k << 10)] = c;
        }
    }
    float lmu = g_logmu[r];
    int jcol = (bb << 5) + w;                 // column this warp combines
    float lnu = g_lognu[(n << 10) + jcol];
    float u_prev = 0.f;
    __syncthreads();

    for (int it = 0; it < MAX_ITER; ++it) {
        // ---- stage scaled v ----
        shvs[tid] = __ldcg(&g_v[(n << 10) + tid]) * L2E_EPS;
        __syncthreads();

        // ---- u-phase: warp-per-row LSE over SMEM (2 chunks of 16/lane) ----
        const float* trow = tile + (w << 10);
        float t[16];
        float m1 = -3.0e38f;
#pragma unroll
        for (int k = 0; k < 4; ++k) {
            int idx = (lane << 2) + (k << 7);
            float4 c = *(const float4*)(trow + idx);
            float4 v = *(const float4*)(shvs + idx);
            float a0 = v.x - c.x, a1 = v.y - c.y, a2 = v.z - c.z, a3 = v.w - c.w;
            t[(k << 2) + 0] = a0; t[(k << 2) + 1] = a1;
            t[(k << 2) + 2] = a2; t[(k << 2) + 3] = a3;
            m1 = fmaxf(m1, fmaxf(fmaxf(a0, a1), fmaxf(a2, a3)));
        }
#pragma unroll
        for (int o = 16; o; o >>= 1) m1 = fmaxf(m1, __shfl_xor_sync(0xffffffffu, m1, o));
        float s1 = 0.f;
#pragma unroll
        for (int q = 0; q < 16; ++q) s1 += ex2(t[q] - m1);

        float m2 = -3.0e38f;
#pragma unroll
        for (int k = 4; k < 8; ++k) {
            int idx = (lane << 2) + (k << 7);
            float4 c = *(const float4*)(trow + idx);
            float4 v = *(const float4*)(shvs + idx);
            float a0 = v.x - c.x, a1 = v.y - c.y, a2 = v.z - c.z, a3 = v.w - c.w;
            t[((k - 4) << 2) + 0] = a0; t[((k - 4) << 2) + 1] = a1;
            t[((k - 4) << 2) + 2] = a2; t[((k - 4) << 2) + 3] = a3;
            m2 = fmaxf(m2, fmaxf(fmaxf(a0, a1), fmaxf(a2, a3)));
        }
#pragma unroll
        for (int o = 16; o; o >>= 1) m2 = fmaxf(m2, __shfl_xor_sync(0xffffffffu, m2, o));
        float s2 = 0.f;
#pragma unroll
        for (int q = 0; q < 16; ++q) s2 += ex2(t[q] - m2);

        float M = fmaxf(m1, m2);
        float S = s1 * ex2(m1 - M) + s2 * ex2(m2 - M);
#pragma unroll
        for (int o = 16; o; o >>= 1) S += __shfl_xor_sync(0xffffffffu, S, o);

        float u_new = EPSF * lmu - EPSLN2 * (M + lg2(S));
        float du = fabsf(u_new - u_prev);
        u_prev = u_new;
        if (lane == 0) {
            sus[w] = u_new * L2E_EPS;
            sdu[w] = du;
            __stcg(&g_u[r], u_new);
        }
        __syncthreads();
        if (tid == 0) {
            float e = 0.f;
#pragma unroll
            for (int q = 0; q < 32; ++q) e += sdu[q];   // fixed order
            __stcg(&g_errPart[b], e);
        }

        // ---- v-phase local partials: thread-per-column over own 32 rows ----
        {
            float ta[16];
            float mA = -3.0e38f;
#pragma unroll
            for (int i = 0; i < 16; ++i) {
                float a = sus[i] - tile[(i << 10) + tid];
                ta[i] = a; mA = fmaxf(mA, a);
            }
            float sA = 0.f;
#pragma unroll
            for (int i = 0; i < 16; ++i) sA += ex2(ta[i] - mA);
            float mB = -3.0e38f;
#pragma unroll
            for (int i = 16; i < 32; ++i) {
                float a = sus[i] - tile[(i << 10) + tid];
                ta[i - 16] = a; mB = fmaxf(mB, a);
            }
            float sB = 0.f;
#pragma unroll
            for (int i = 0; i < 16; ++i) sB += ex2(ta[i] - mB);
            float Mv = fmaxf(mA, mB);
            float Sv = sA * ex2(mA - Mv) + sB * ex2(mB - Mv);
            __stcg(&g_part[(((n << 10) + tid) << 5) + bb], make_float2(Mv, Sv));
        }
        grid_barrier();

        // ---- combine partials: warp w -> column jcol, fixed shfl order ----
        {
            float2 p = __ldcg(&g_part[(((n << 10) + jcol) << 5) + lane]);
            float Mg = p.x;
#pragma unroll
            for (int o = 16; o; o >>= 1) Mg = fmaxf(Mg, __shfl_xor_sync(0xffffffffu, Mg, o));
            float Sg = p.y * ex2(p.x - Mg);
#pragma unroll
            for (int o = 16; o; o >>= 1) Sg += __shfl_xor_sync(0xffffffffu, Sg, o);
            float v_new = EPSF * lnu - EPSLN2 * (Mg + lg2(Sg));
            if (lane == 0) __stcg(&g_v[(n << 10) + jcol], v_new);
        }

        if (b == 0 && tid == 0) {
            float e = 0.f;
#pragma unroll
            for (int q = 0; q < SBLOCKS; ++q) e += __ldcg(&g_errPart[q]);   // fixed order
            __stcg(&g_done, (e * 0.25f < THRESHF) ? 1 : 0);
        }
        grid_barrier();

        if (tid == 0) sdone = __ldcg(&g_done);
        __syncthreads();
        if (sdone) break;   // uniform across grid
    }
}

// ----------------------------- kernel 3: pi + per-row cost partials ---------
__global__ void k_pi(const float* __restrict__ C, float* __restrict__ pi) {
    __shared__ __align__(16) float vs[P];
    __shared__ float red[256];
    int r = blockIdx.x;
    int n = r >> 10;
    int tid = threadIdx.x;   // 256
    for (int e = tid; e < P; e += 256) vs[e] = g_v[(n << 10) + e];
    float u = g_u[r] * L2E_EPS;
    __syncthreads();

    const float4* crow = (const float4*)(C + ((size_t)r << 10));
    float4* prow = (float4*)(pi + ((size_t)r << 10));
    float4 c = __ldcg(&crow[tid]);
    float4 v = *(const float4*)&vs[tid << 2];
    float4 p;
    p.x = ex2(fmaf(v.x, L2E_EPS, u) - c.x * L2E_EPS);
    p.y = ex2(fmaf(v.y, L2E_EPS, u) - c.y * L2E_EPS);
    p.z = ex2(fmaf(v.z, L2E_EPS, u) - c.z * L2E_EPS);
    p.w = ex2(fmaf(v.w, L2E_EPS, u) - c.w * L2E_EPS);
    __stcg(&prow[tid], p);
    float acc = p.x * c.x + p.y * c.y + p.z * c.z + p.w * c.w;

    red[tid] = acc;
    __syncthreads();
    for (int o = 128; o; o >>= 1) {
        if (tid < o) red[tid] += red[tid + o];
        __syncthreads();
    }
    if (tid == 0) g_rowPart[r] = red[0];
}

// ----------------------------- kernel 4: deterministic cost reduce ----------
__global__ void k_final(float* __restrict__ cost) {
    int tid = threadIdx.x;   // 128
    int n = tid >> 5, lane = tid & 31;
    float s = 0.f;
#pragma unroll
    for (int q = 0; q < 32; ++q) s += g_rowPart[(n << 10) + lane + (q << 5)];
#pragma unroll
    for (int o = 16; o; o >>= 1) s += __shfl_xor_sync(0xffffffffu, s, o);
    if (lane == 0) cost[n] = s;
}

// ----------------------------- launch ---------------------------------------
#define SINK_SMEM ((32*1024 + 1024 + 32 + 32) * 4)

extern "C" void kernel_launch(void* const* d_in, const int* in_sizes, int n_in,
                              void* d_out, int out_size) {
    const float* x  = (const float*)d_in[0];
    const float* y  = (const float*)d_in[1];
    const float* wx = (const float*)d_in[2];
    const float* wy = (const float*)d_in[3];

    float* out  = (float*)d_out;
    float* cost = out;                 // [4]
    float* pi   = out + NB;            // [4,1024,1024]
    float* C    = out + NB + PLANE;    // [4,1024,1024]

    cudaFuncSetAttribute(k_sink, cudaFuncAttributeMaxDynamicSharedMemorySize, SINK_SMEM);

    k_init<<<4, 1024>>>(wx, wy);
    dim3 gc(32, 32, 4);
    k_cost<<<gc, 256>>>(x, y, C);
    k_sink<<<SBLOCKS, STHREADS, SINK_SMEM>>>(C);
    k_pi<<<NB * P, 256>>>(C, pi);
    k_final<<<1, 128>>>(cost);
}